// round 14
// baseline (speedup 1.0000x reference)
#include <cuda_runtime.h>
#include <cuda_fp16.h>
#include <cstdint>

// Problem constants (fixed shapes from the reference)
#define BATCH 2
#define DIMD  128
#define NCLS  19
#define NP    3600    // 60*60 anchors
#define NP_PAD 3712   // 29 tiles of 128
#define NN    57600   // 240*240 negatives
#define INV_TEMP 10.0f
// A is prescaled by 10*log2(e) so the epilogue uses a single EX2 per element.
#define A_SCALE 14.4269504088896340736f
#define GAMMA 0.75f
#define EPS 1e-8f

// GEMM config: each CTA owns one 128-row A tile and streams NTPC N-tiles of 128
#define NTPC 18
#define GROUPS_N 25   // 25*18*128 = 57600

// idesc: kind::f16, dtype F32 (1<<4), a/b F16 (0), N=128 (16<<17), M=128 (8<<24)
#define MMA_IDESC 0x08200010u

// Does this device-compilation pass have the sm_103a arch-specific features?
#if defined(__CUDA_ARCH__) && \
    (defined(__CUDA_ARCH_FEAT_SM103_ALL) || \
     (defined(__CUDA_ARCH_SPECIFIC__) && (__CUDA_ARCH_SPECIFIC__ == 1030)) || \
     (defined(__CUDA_ARCH_FAMILY_SPECIFIC__) && (__CUDA_ARCH_FAMILY_SPECIFIC__ == 1030)))
#define HAVE_TC5 1
#else
#define HAVE_TC5 0
#endif

// Scratch (device globals, no allocation)
__device__ float g_neg_logits[BATCH][NP];
__device__ float g_pos1[BATCH][NP];
__device__ float g_mask1[BATCH][NP];
__device__ int   g_labels1[BATCH][NP];
__device__ int   g_neg_labels[BATCH][NN];
__device__ __half g_Ah[BATCH][NP_PAD][DIMD];  // f1^T * 10*log2(e), f16
__device__ __half g_Bh[BATCH][NN][DIMD];      // nf^T, f16

__device__ __forceinline__ float ex2f(float x) {
    float r;
    asm("ex2.approx.ftz.f32 %0, %1;" : "=f"(r) : "f"(x));
    return r;
}

// ---------------------------------------------------------------------------
// Fused prep kernel: one launch, blocks partitioned into 4 independent
// sections. Conv sections use 64(p) x 32(d) tiles with float4 loads.
//   [0, 7200)      : conv-transpose B  (nf fp32 [D][NN] -> f16 [NN][D])
//   [7200, 7664)   : conv-transpose A  (f1 -> f16 [NP_PAD][D], *A_SCALE)
//   [7664, 8114)   : neg-label argmax
//   [8114, 8144)   : anchor prep (labels1/mask1/pos1/zero)
// ---------------------------------------------------------------------------
#define NB_CONVB 7200    // (NN/64) * (DIMD/32) * BATCH = 900*4*2
#define NB_CONVA 464     // (NP_PAD/64) * 4 * 2 = 58*4*2
#define NB_NEG   450     // 225 per batch
#define NB_ANCH  30      // 15 per batch
#define NB_TOTAL (NB_CONVB + NB_CONVA + NB_NEG + NB_ANCH)

// 64 p-cols x 32 d-rows per block; float4 loads, __half2 stores.
__device__ __forceinline__ void conv_section64(const float* __restrict__ s,
                                               __half* __restrict__ d,
                                               int ncols, int nrows_pad, float scale,
                                               int bx, int by, int tid,
                                               float (*tile)[65]) {
    const int px = bx * 64;   // source col == dst row
    const int dy = by * 32;   // d dimension
    // load 32 d-rows x 64 p-cols (16 float4 per row, 512 float4 total)
    #pragma unroll
    for (int i = 0; i < 2; i++) {
        int q   = tid + i * 256;      // 0..511
        int row = q >> 4;             // d-local 0..31
        int c4  = (q & 15) * 4;       // p-local (float4 aligned)
        int p   = px + c4;
        float4 v;
        if (p < ncols)   // ncols % 4 == 0 -> whole float4 in bounds
            v = *reinterpret_cast<const float4*>(&s[(size_t)(dy + row) * ncols + p]);
        else
            v = make_float4(0.f, 0.f, 0.f, 0.f);
        tile[row][c4]     = v.x * scale;
        tile[row][c4 + 1] = v.y * scale;
        tile[row][c4 + 2] = v.z * scale;
        tile[row][c4 + 3] = v.w * scale;
    }
    __syncthreads();
    // write: 64 p-rows x 16 d-pairs = 1024 __half2
    #pragma unroll
    for (int i = 0; i < 4; i++) {
        int q    = tid + i * 256;     // 0..1023
        int prow = q >> 4;            // p-local 0..63
        int pr   = q & 15;            // d-pair 0..15
        int p = px + prow;
        if (p < nrows_pad) {
            __half2 h = __floats2half2_rn(tile[pr * 2][prow], tile[pr * 2 + 1][prow]);
            *reinterpret_cast<__half2*>(d + (size_t)p * DIMD + dy + pr * 2) = h;
        }
    }
}

__global__ __launch_bounds__(256)
void prep_all_kernel(const float* __restrict__ feats_view1,
                     const float* __restrict__ pos_feats1,
                     const float* __restrict__ pos_feats2,
                     const float* __restrict__ pl1,
                     const float* __restrict__ pl2,
                     const float* __restrict__ npl,
                     __half* __restrict__ pA,
                     __half* __restrict__ pB) {
    __shared__ float tile[32][65];
    const int bid = blockIdx.x;
    const int tid = threadIdx.x;

    if (bid < NB_CONVB) {
        // B: nf [D][NN] -> f16 [NN][D]
        int bz  = bid / (NB_CONVB / BATCH);
        int rem = bid % (NB_CONVB / BATCH);
        int by  = rem / (NN / 64);
        int bx  = rem % (NN / 64);
        conv_section64(feats_view1 + (size_t)bz * DIMD * NN,
                       pB + (size_t)bz * NN * DIMD,
                       NN, NN, 1.0f, bx, by, tid, tile);
    } else if (bid < NB_CONVB + NB_CONVA) {
        // A: f1 [D][NP] -> f16 [NP_PAD][D] * A_SCALE
        int b2  = bid - NB_CONVB;
        int bz  = b2 / (NB_CONVA / BATCH);
        int rem = b2 % (NB_CONVA / BATCH);
        int by  = rem / (NP_PAD / 64);
        int bx  = rem % (NP_PAD / 64);
        conv_section64(pos_feats1 + (size_t)bz * DIMD * NP,
                       pA + (size_t)bz * NP_PAD * DIMD,
                       NP, NP_PAD, A_SCALE, bx, by, tid, tile);
    } else if (bid < NB_CONVB + NB_CONVA + NB_NEG) {
        // neg-label argmax
        int b3 = bid - NB_CONVB - NB_CONVA;
        int b  = b3 / (NB_NEG / BATCH);
        int n  = (b3 % (NB_NEG / BATCH)) * 256 + tid;
        const float* nplb = npl + (size_t)b * NCLS * NN;
        float best = -1e30f; int bi = 0;
        #pragma unroll
        for (int c = 0; c < NCLS; c++) {
            float v = nplb[c * NN + n];
            if (v > best) { best = v; bi = c; }
        }
        g_neg_labels[b][n] = bi;
    } else {
        // anchor prep
        int b4 = bid - NB_CONVB - NB_CONVA - NB_NEG;
        int b  = b4 / (NB_ANCH / BATCH);
        int p  = (b4 % (NB_ANCH / BATCH)) * 256 + tid;
        if (p >= NP) return;

        const float* pl1b = pl1 + (size_t)b * NCLS * NP;
        const float* pl2b = pl2 + (size_t)b * NCLS * NP;

        float best = -1e30f; int bi = 0;
        #pragma unroll
        for (int c = 0; c < NCLS; c++) {
            float v = pl1b[c * NP + p];
            if (v > best) { best = v; bi = c; }
        }
        g_labels1[b][p] = bi;

        int mi = -1;
        #pragma unroll
        for (int c = 0; c < NCLS; c++) {
            float a = pl1b[c * NP + p];
            float q = pl2b[c * NP + p];
            if (mi < 0 && (a < q) && (q > GAMMA)) mi = c;
        }
        g_mask1[b][p] = (mi < 0) ? 0.0f : (float)mi;

        const float* f1b = pos_feats1 + (size_t)b * DIMD * NP;
        const float* f2b = pos_feats2 + (size_t)b * DIMD * NP;
        float acc = 0.0f;
        #pragma unroll 8
        for (int d = 0; d < DIMD; d++)
            acc += f1b[d * NP + p] * f2b[d * NP + p];
        g_pos1[b][p] = acc * INV_TEMP;

        g_neg_logits[b][p] = 0.0f;
    }
}

// ---------------------------------------------------------------------------
// SMEM layout (bytes, from 1024-aligned base) -- tcgen05 path
// ---------------------------------------------------------------------------
#define OFF_A     0u
#define OFF_B     32768u
#define OFF_NLAB  98304u      // NTPC * 128 ints
#define OFF_TPTR  107520u
#define OFF_MBAR  107528u
#define SMEM_REQ  (107544 + 1024)

#if HAVE_TC5
// ---------------------------------------------------------------------------
// tcgen05 helpers (sm_103a-only pass)
// ---------------------------------------------------------------------------
static constexpr uint64_t SMEM_DESC_BASE_SW128 =
    (uint64_t(2)  << 61) | (uint64_t(1) << 46) | (uint64_t(64) << 32) | (uint64_t(1) << 16);

__device__ __forceinline__ uint64_t make_desc(uint32_t saddr) {
    return SMEM_DESC_BASE_SW128 | ((uint64_t)(saddr >> 4) & 0x3FFF);
}

__device__ __forceinline__ bool elect1() {
    uint32_t p;
    asm volatile("{\n\t.reg .pred p;\n\telect.sync _|p, 0xFFFFFFFF;\n\tselp.b32 %0, 1, 0, p;\n\t}"
                 : "=r"(p));
    return p != 0;
}

__device__ __forceinline__ void mma_f16_ss(uint32_t d, uint64_t a, uint64_t b,
                                           uint32_t en) {
    asm volatile(
        "{\n\t.reg .pred p;\n\tsetp.ne.u32 p, %4, 0;\n\t"
        "tcgen05.mma.cta_group::1.kind::f16 [%0], %1, %2, %3, {%5,%5,%5,%5}, p;\n\t}"
        :: "r"(d), "l"(a), "l"(b), "r"(MMA_IDESC), "r"(en), "r"(0u)
        : "memory");
}

__device__ __forceinline__ void mbar_init(uint32_t a, uint32_t cnt) {
    asm volatile("mbarrier.init.shared.b64 [%0], %1;" :: "r"(a), "r"(cnt) : "memory");
}
__device__ __forceinline__ void mbar_wait(uint32_t a, uint32_t ph) {
    asm volatile(
        "{\n\t.reg .pred P1;\n\t"
        "W0_%=:\n\t"
        "mbarrier.try_wait.parity.acquire.cta.shared::cta.b64 P1, [%0], %1, 0x989680;\n\t"
        "@P1 bra W1_%=;\n\t"
        "bra W0_%=;\n\t"
        "W1_%=:\n\t}"
        :: "r"(a), "r"(ph) : "memory");
}

#define TC_ALLOC(sa, n)  asm volatile("tcgen05.alloc.cta_group::1.sync.aligned.shared::cta.b32 [%0], %1;" :: "r"(sa), "r"(n) : "memory")
#define TC_RELINQ()      asm volatile("tcgen05.relinquish_alloc_permit.cta_group::1.sync.aligned;")
#define TC_DEALLOC(t, n) asm volatile("tcgen05.dealloc.cta_group::1.sync.aligned.b32 %0, %1;" :: "r"(t), "r"(n))
#define TC_COMMIT(mb)    asm volatile("tcgen05.commit.cta_group::1.mbarrier::arrive::one.shared::cluster.b64 [%0];" :: "r"(mb) : "memory")
#define TC_WAIT_LD()     asm volatile("tcgen05.wait::ld.sync.aligned;" ::: "memory")
#define TC_FENCE_AFTER() asm volatile("tcgen05.fence::after_thread_sync;" ::: "memory")
#define TC_FENCE_BEFORE() asm volatile("tcgen05.fence::before_thread_sync;" ::: "memory")
#define PROXY_FENCE()    asm volatile("fence.proxy.async.shared::cta;" ::: "memory")
#define CP_COMMIT()      asm volatile("cp.async.commit_group;" ::: "memory")
#define CP_WAIT0()       asm volatile("cp.async.wait_group 0;" ::: "memory")
#define CP_WAIT1()       asm volatile("cp.async.wait_group 1;" ::: "memory")

#define LDTM_X32(r, a) \
    asm volatile("tcgen05.ld.sync.aligned.32x32b.x32.b32 " \
        "{%0, %1, %2, %3, %4, %5, %6, %7, " \
        " %8, %9, %10, %11, %12, %13, %14, %15, " \
        " %16, %17, %18, %19, %20, %21, %22, %23, " \
        " %24, %25, %26, %27, %28, %29, %30, %31}, [%32];" \
        : "=r"((r)[0]),  "=r"((r)[1]),  "=r"((r)[2]),  "=r"((r)[3]), \
          "=r"((r)[4]),  "=r"((r)[5]),  "=r"((r)[6]),  "=r"((r)[7]), \
          "=r"((r)[8]),  "=r"((r)[9]),  "=r"((r)[10]), "=r"((r)[11]), \
          "=r"((r)[12]), "=r"((r)[13]), "=r"((r)[14]), "=r"((r)[15]), \
          "=r"((r)[16]), "=r"((r)[17]), "=r"((r)[18]), "=r"((r)[19]), \
          "=r"((r)[20]), "=r"((r)[21]), "=r"((r)[22]), "=r"((r)[23]), \
          "=r"((r)[24]), "=r"((r)[25]), "=r"((r)[26]), "=r"((r)[27]), \
          "=r"((r)[28]), "=r"((r)[29]), "=r"((r)[30]), "=r"((r)[31]) \
        : "r"(a))

// cp.async a [128 rows x 128 f16] row-major global tile into K-blocked
// SW128 SMEM: two blocks of [128 rows x 64 f16] (128B rows, XOR swizzle).
__device__ __forceinline__ void cp_tile128(const __half* __restrict__ g,
                                           uint32_t s_base, int tid) {
    #pragma unroll
    for (int i = 0; i < 8; i++) {
        int q = tid + i * 256;         // 16B-chunk index, 2048 total
        int r = q >> 4;                // row 0..127
        int c = q & 15;                // chunk 0..15
        int blk = c >> 3;
        int cc  = (c & 7) ^ (r & 7);
        uint32_t sa = s_base + blk * 16384u + (uint32_t)r * 128u + (uint32_t)cc * 16u;
        const void* ga = (const void*)(g + (size_t)r * 128 + c * 8);
        asm volatile("cp.async.cg.shared.global [%0], [%1], 16;"
                     :: "r"(sa), "l"(ga) : "memory");
    }
}

// exp2 of two fp32 values via one MUFU op (f16x2): inputs are log2-domain
// scores (|x| small); independent per-element rounding -> error ~1e-5 on sums.
__device__ __forceinline__ float2 ex2_pair(float lo, float hi) {
    uint32_t h;
    asm("cvt.rn.f16x2.f32 %0, %1, %2;" : "=r"(h) : "f"(hi), "f"(lo));
    asm("ex2.approx.f16x2 %0, %0;" : "+r"(h));
    return __half22float2(*reinterpret_cast<__half2*>(&h));
}
#endif  // HAVE_TC5

#if !HAVE_TC5
// ---------------------------------------------------------------------------
// Fallback helpers: mma.sync m16n8k16 f16 (compiles on any >= sm_80 target)
// ---------------------------------------------------------------------------
__device__ __forceinline__ void ldmx4(uint32_t* r, uint32_t saddr) {
    asm volatile("ldmatrix.sync.aligned.m8n8.x4.shared.b16 {%0,%1,%2,%3}, [%4];"
                 : "=r"(r[0]), "=r"(r[1]), "=r"(r[2]), "=r"(r[3]) : "r"(saddr));
}
__device__ __forceinline__ void mma16816(float* c, const uint32_t* a, const uint32_t* b) {
    asm volatile("mma.sync.aligned.m16n8k16.row.col.f32.f16.f16.f32 "
                 "{%0,%1,%2,%3}, {%4,%5,%6,%7}, {%8,%9}, {%0,%1,%2,%3};"
                 : "+f"(c[0]), "+f"(c[1]), "+f"(c[2]), "+f"(c[3])
                 : "r"(a[0]), "r"(a[1]), "r"(a[2]), "r"(a[3]), "r"(b[0]), "r"(b[1]));
}
// swizzled element offset in a flat [r][128] f16 tile (16B-chunk XOR swizzle)
__device__ __forceinline__ int swz(int r, int k) {
    return r * 128 + ((((k) >> 3) ^ (r & 7)) << 3) + (k & 7);
}
#endif  // !HAVE_TC5

// ---------------------------------------------------------------------------
// GEMM + fused masked-exp row-sum epilogue. One kernel name, two bodies:
// tcgen05 (sm_103a cubin) or mma.sync (virtual-arch / JIT fallback).
// Grid: (GROUPS_N, NP_PAD/128, BATCH), 256 threads, SMEM_REQ dynamic smem.
// ---------------------------------------------------------------------------
__global__ __launch_bounds__(256, 2)
void neg_gemm_kernel() {
    extern __shared__ __align__(16) uint8_t dynsmem[];
    uint8_t* smem = (uint8_t*)(((uintptr_t)dynsmem + 1023) & ~(uintptr_t)1023);

    const int b      = blockIdx.z;
    const int p0     = blockIdx.y * 128;
    const int n_base = blockIdx.x * (NTPC * 128);
    const int tid    = threadIdx.x;
    const int wid    = tid >> 5;
    const int lane   = tid & 31;

#if HAVE_TC5
    // ======================= tcgen05 pipelined path =======================
    const uint32_t sb    = (uint32_t)__cvta_generic_to_shared(smem);
    const uint32_t mbar0 = sb + OFF_MBAR;
    const uint32_t mbar1 = sb + OFF_MBAR + 8;
    int* nlabAll = (int*)(smem + OFF_NLAB);

    if (wid == 0) {
        TC_ALLOC(sb + OFF_TPTR, 256u);
        TC_RELINQ();
    }
    if (tid == 0) { mbar_init(mbar0, 1); mbar_init(mbar1, 1); }

    // prologue: async-load A + B0 (group 0), B1 (group 1); labels for all tiles
    cp_tile128(&g_Ah[b][p0][0], sb + OFF_A, tid);
    cp_tile128(&g_Bh[b][n_base][0], sb + OFF_B, tid);
    CP_COMMIT();
    cp_tile128(&g_Bh[b][n_base + 128][0], sb + OFF_B + 32768u, tid);
    CP_COMMIT();
    #pragma unroll
    for (int i = 0; i < NTPC * 128 / 256; i++)
        nlabAll[tid + i * 256] = g_neg_labels[b][n_base + tid + i * 256];

    CP_WAIT1();        // A + B0 resident
    PROXY_FENCE();
    __syncthreads();

    const uint32_t tmem_base = *reinterpret_cast<uint32_t*>(smem + OFF_TPTR);
    const uint64_t adesc = make_desc(sb + OFF_A);

    // issue MMA for tile 0
    if (wid == 0) {
        TC_FENCE_AFTER();
        if (elect1()) {
            uint64_t bdesc = make_desc(sb + OFF_B);
            #pragma unroll
            for (int kk = 0; kk < 8; kk++) {
                uint64_t koff = (uint64_t)((kk >> 2) * 1024 + (kk & 3) * 2);
                mma_f16_ss(tmem_base, adesc + koff, bdesc + koff, kk > 0);
            }
            TC_COMMIT(mbar0);
        }
    }

    const int myrow = (wid & 3) * 32 + lane;
    const int myp   = p0 + myrow;
    const int lp    = (myp < NP) ? g_labels1[b][myp] : -1;
    float rs0 = 0.0f, rs1 = 0.0f;
    const int cbase = (wid >> 2) * 64;  // warpgroup n-column split

    for (int nt = 1; nt <= NTPC; nt++) {
        const int prev = nt - 1;

        // MMA prev done (issued one epilogue ago -> fast-path wait)
        mbar_wait((prev & 1) ? mbar1 : mbar0, (prev >> 1) & 1);

        if (nt < NTPC) {
            // prefetch B[nt+1] into the buffer MMA prev just released
            if (nt + 1 < NTPC) {
                cp_tile128(&g_Bh[b][n_base + (nt + 1) * 128][0],
                           sb + OFF_B + (uint32_t)((nt + 1) & 1) * 32768u, tid);
                CP_COMMIT();
                CP_WAIT1();      // B[nt] resident
            } else {
                CP_WAIT0();      // B[nt] resident, no more prefetch
            }
            PROXY_FENCE();
        }
        __syncthreads();

        if (nt < NTPC && wid == 0) {
            TC_FENCE_AFTER();
            if (elect1()) {
                uint64_t bdesc = make_desc(sb + OFF_B + (uint32_t)(nt & 1) * 32768u);
                uint32_t dtm = tmem_base + (nt & 1) * 128;
                #pragma unroll
                for (int kk = 0; kk < 8; kk++) {
                    uint64_t koff = (uint64_t)((kk >> 2) * 1024 + (kk & 3) * 2);
                    mma_f16_ss(dtm, adesc + koff, bdesc + koff, kk > 0);
                }
                TC_COMMIT((nt & 1) ? mbar1 : mbar0);
            }
        }

        // ---- epilogue tile prev (overlaps MMA nt + prefetch B nt+1) ----
        // Both LDTMs issued back-to-back, ONE wait: a single exposed
        // TMEM-latency window per iteration instead of two.
        TC_FENCE_AFTER();
        const int* nl = nlabAll + prev * 128;
        const uint32_t dtm_prev = tmem_base + (prev & 1) * 128;
        uint32_t r0[32], r1[32];
        LDTM_X32(r0, dtm_prev + cbase);
        LDTM_X32(r1, dtm_prev + cbase + 32);
        TC_WAIT_LD();
        #pragma unroll
        for (int j = 0; j < 32; j += 2) {
            float2 e = ex2_pair(__uint_as_float(r0[j]), __uint_as_float(r0[j + 1]));
            rs0 += (lp != nl[cbase + j])     ? e.x : 0.0f;
            rs1 += (lp != nl[cbase + j + 1]) ? e.y : 0.0f;
        }
        #pragma unroll
        for (int j = 0; j < 32; j += 2) {
            float2 e = ex2_pair(__uint_as_float(r1[j]), __uint_as_float(r1[j + 1]));
            rs0 += (lp != nl[cbase + 32 + j])     ? e.x : 0.0f;
            rs1 += (lp != nl[cbase + 32 + j + 1]) ? e.y : 0.0f;
        }
        TC_FENCE_BEFORE();
    }

    if (myp < NP)
        atomicAdd(&g_neg_logits[b][myp], rs0 + rs1);

    __syncthreads();
    if (wid == 0) TC_DEALLOC(tmem_base, 256u);

#else
    // ======================= mma.sync fallback path =======================
    __half* Asm = (__half*)smem;             // 32KB (flat [128][128] swz)
    __half* Bsm = (__half*)(smem + 32768u);  // 32KB
    int* nlab = (int*)(smem + 65536u);       // 128 ints

    const int wm = wid & 3;    // m sub-block (32 rows)
    const int wn = wid >> 2;   // n sub-block (64 cols)

    const __half* Ag = &g_Ah[b][p0][0];
    #pragma unroll
    for (int i = 0; i < 8; i++) {
        int q = tid + i * 256;
        int r = q >> 4;
        int c = q & 15;
        uint4 v = *reinterpret_cast<const uint4*>(Ag + (size_t)r * 128 + c * 8);
        int sc = c ^ (r & 7);
        *reinterpret_cast<uint4*>(Asm + r * 128 + sc * 8) = v;
    }

    int lp2[2][2];
    #pragma unroll
    for (int mi = 0; mi < 2; mi++) {
        int base = p0 + wm * 32 + mi * 16 + (lane >> 2);
        lp2[mi][0] = (base     < NP) ? g_labels1[b][base]     : -1;
        lp2[mi][1] = (base + 8 < NP) ? g_labels1[b][base + 8] : -1;
    }
    float rs[2][2] = {{0.f, 0.f}, {0.f, 0.f}};

    const uint32_t asmb = (uint32_t)__cvta_generic_to_shared(Asm);
    const uint32_t bsmb = (uint32_t)__cvta_generic_to_shared(Bsm);

    for (int nt = 0; nt < NTPC; nt++) {
        const int n0 = n_base + nt * 128;
        __syncthreads();
        const __half* Bg = &g_Bh[b][n0][0];
        #pragma unroll
        for (int i = 0; i < 8; i++) {
            int q = tid + i * 256;
            int r = q >> 4;
            int c = q & 15;
            uint4 v = *reinterpret_cast<const uint4*>(Bg + (size_t)r * 128 + c * 8);
            int sc = c ^ (r & 7);
            *reinterpret_cast<uint4*>(Bsm + r * 128 + sc * 8) = v;
        }
        if (tid < 128) nlab[tid] = g_neg_labels[b][n0 + tid];
        __syncthreads();

        float acc[2][8][4];
        #pragma unroll
        for (int mi = 0; mi < 2; mi++)
            #pragma unroll
            for (int ni = 0; ni < 8; ni++)
                #pragma unroll
                for (int x = 0; x < 4; x++) acc[mi][ni][x] = 0.0f;

        #pragma unroll
        for (int kk = 0; kk < 8; kk++) {
            const int k0 = kk * 16;
            uint32_t afr[2][4];
            #pragma unroll
            for (int mi = 0; mi < 2; mi++) {
                int row = wm * 32 + mi * 16 + (lane & 7) + 8 * ((lane >> 3) & 1);
                int k8  = k0 + 8 * (lane >> 4);
                ldmx4(afr[mi], asmb + 2 * swz(row, k8));
            }
            uint32_t bfr[8][2];
            #pragma unroll
            for (int nj = 0; nj < 4; nj++) {
                int nrow = wn * 64 + nj * 16 + (lane & 7) + 8 * (lane >> 4);
                int k8   = k0 + 8 * ((lane >> 3) & 1);
                uint32_t r4[4];
                ldmx4(r4, bsmb + 2 * swz(nrow, k8));
                bfr[nj * 2][0]     = r4[0]; bfr[nj * 2][1]     = r4[1];
                bfr[nj * 2 + 1][0] = r4[2]; bfr[nj * 2 + 1][1] = r4[3];
            }
            #pragma unroll
            for (int mi = 0; mi < 2; mi++)
                #pragma unroll
                for (int ni = 0; ni < 8; ni++)
                    mma16816(acc[mi][ni], afr[mi], bfr[ni]);
        }

        #pragma unroll
        for (int ni = 0; ni < 8; ni++) {
            int c0  = wn * 64 + ni * 8 + 2 * (lane & 3);
            int ln0 = nlab[c0];
            int ln1 = nlab[c0 + 1];
            #pragma unroll
            for (int mi = 0; mi < 2; mi++) {
                float e0 = ex2f(acc[mi][ni][0]);
                float e1 = ex2f(acc[mi][ni][1]);
                float e2 = ex2f(acc[mi][ni][2]);
                float e3 = ex2f(acc[mi][ni][3]);
                rs[mi][0] += (lp2[mi][0] != ln0 ? e0 : 0.f) + (lp2[mi][0] != ln1 ? e1 : 0.f);
                rs[mi][1] += (lp2[mi][1] != ln0 ? e2 : 0.f) + (lp2[mi][1] != ln1 ? e3 : 0.f);
            }
        }
    }

    #pragma unroll
    for (int mi = 0; mi < 2; mi++)
        #pragma unroll
        for (int h = 0; h < 2; h++) {
            float s = rs[mi][h];
            s += __shfl_xor_sync(0xffffffffu, s, 1);
            s += __shfl_xor_sync(0xffffffffu, s, 2);
            int p = p0 + wm * 32 + mi * 16 + (lane >> 2) + h * 8;
            if ((lane & 3) == 0 && p < NP)
                atomicAdd(&g_neg_logits[b][p], s);
        }
#endif
}

// ---------------------------------------------------------------------------
// Finalize (fast intrinsics; tiny kernel)
// ---------------------------------------------------------------------------
__global__ void finalize_kernel(float* __restrict__ out) {
    __shared__ float s_num[1024];
    __shared__ float s_den[1024];
    const int tid = threadIdx.x;
    float total = 0.0f;

    for (int b = 0; b < BATCH; b++) {
        float num = 0.0f, den = 0.0f;
        for (int p = tid; p < NP; p += 1024) {
            float pe  = __expf(g_pos1[b][p]);
            float neg = g_neg_logits[b][p];
            float lossn = -__logf(pe / (pe + neg + EPS) + EPS);
            float m = g_mask1[b][p];
            num += m * lossn;
            den += m;
        }
        s_num[tid] = num; s_den[tid] = den;
        __syncthreads();
        for (int s = 512; s > 0; s >>= 1) {
            if (tid < s) { s_num[tid] += s_num[tid + s]; s_den[tid] += s_den[tid + s]; }
            __syncthreads();
        }
        if (tid == 0) total += s_num[0] / (s_den[0] + EPS);
        __syncthreads();
    }
    if (tid == 0) out[0] = 0.1f * total;
}

// ---------------------------------------------------------------------------
extern "C" void kernel_launch(void* const* d_in, const int* in_sizes, int n_in,
                              void* d_out, int out_size) {
    const float* feats_view1 = (const float*)d_in[0];  // [2,128,240,240]
    const float* pos_feats1  = (const float*)d_in[1];  // [2,128,60,60]
    const float* pos_feats2  = (const float*)d_in[2];  // [2,128,60,60]
    const float* plog1       = (const float*)d_in[3];  // [2,19,60,60]
    const float* plog2       = (const float*)d_in[4];  // [2,19,60,60]
    const float* neg_plog    = (const float*)d_in[5];  // [2,19,240,240]
    float* out = (float*)d_out;

    static __half* pA = nullptr;
    static __half* pB = nullptr;
    if (!pA) { cudaGetSymbolAddress((void**)&pA, g_Ah); }
    if (!pB) { cudaGetSymbolAddress((void**)&pB, g_Bh); }

    static bool attr_set = false;
    if (!attr_set) {
        cudaFuncSetAttribute(neg_gemm_kernel,
                             cudaFuncAttributeMaxDynamicSharedMemorySize, SMEM_REQ);
        attr_set = true;
    }

    prep_all_kernel<<<NB_TOTAL, 256>>>(feats_view1, pos_feats1, pos_feats2,
                                       plog1, plog2, neg_plog, pA, pB);
    {
        dim3 grid(GROUPS_N, NP_PAD / 128, BATCH);   // (25, 29, 2)
        neg_gemm_kernel<<<grid, 256, SMEM_REQ>>>();
    }
    finalize_kernel<<<1, 1024>>>(out);
}

// round 15
// speedup vs baseline: 1.0376x; 1.0376x over previous
#include <cuda_runtime.h>
#include <cuda_fp16.h>
#include <cstdint>

// Problem constants (fixed shapes from the reference)
#define BATCH 2
#define DIMD  128
#define NCLS  19
#define NP    3600    // 60*60 anchors
#define NP_PAD 3712   // 29 tiles of 128
#define NN    57600   // 240*240 negatives
#define INV_TEMP 10.0f
// A is prescaled by 10*log2(e) so the epilogue uses a single EX2 per element.
#define A_SCALE 14.4269504088896340736f
#define GAMMA 0.75f
#define EPS 1e-8f

// GEMM config: each CTA owns one 128-row A tile and streams NTPC N-tiles of 128
#define NTPC 18
#define GROUPS_N 25   // 25*18*128 = 57600

// idesc: kind::f16, dtype F32 (1<<4), a/b F16 (0), N=128 (16<<17), M=128 (8<<24)
#define MMA_IDESC 0x08200010u

// Does this device-compilation pass have the sm_103a arch-specific features?
#if defined(__CUDA_ARCH__) && \
    (defined(__CUDA_ARCH_FEAT_SM103_ALL) || \
     (defined(__CUDA_ARCH_SPECIFIC__) && (__CUDA_ARCH_SPECIFIC__ == 1030)) || \
     (defined(__CUDA_ARCH_FAMILY_SPECIFIC__) && (__CUDA_ARCH_FAMILY_SPECIFIC__ == 1030)))
#define HAVE_TC5 1
#else
#define HAVE_TC5 0
#endif

// Scratch (device globals, no allocation)
__device__ float g_neg_logits[BATCH][NP];
__device__ float g_pos1[BATCH][NP];
__device__ float g_mask1[BATCH][NP];
__device__ int   g_labels1[BATCH][NP];
__device__ int   g_neg_labels[BATCH][NN];
__device__ __half g_Ah[BATCH][NP_PAD][DIMD];  // f1^T * 10*log2(e), f16
__device__ __half g_Bh[BATCH][NN][DIMD];      // nf^T, f16

__device__ __forceinline__ float ex2f(float x) {
    float r;
    asm("ex2.approx.ftz.f32 %0, %1;" : "=f"(r) : "f"(x));
    return r;
}

// ---------------------------------------------------------------------------
// Fused prep kernel: one launch, blocks partitioned into 4 independent
// sections. Conv sections use 64(p) x 32(d) tiles with float4 loads.
// ---------------------------------------------------------------------------
#define NB_CONVB 7200    // (NN/64) * (DIMD/32) * BATCH = 900*4*2
#define NB_CONVA 464     // (NP_PAD/64) * 4 * 2 = 58*4*2
#define NB_NEG   450     // 225 per batch
#define NB_ANCH  30      // 15 per batch
#define NB_TOTAL (NB_CONVB + NB_CONVA + NB_NEG + NB_ANCH)

// 64 p-cols x 32 d-rows per block; float4 loads, __half2 stores.
__device__ __forceinline__ void conv_section64(const float* __restrict__ s,
                                               __half* __restrict__ d,
                                               int ncols, int nrows_pad, float scale,
                                               int bx, int by, int tid,
                                               float (*tile)[65]) {
    const int px = bx * 64;   // source col == dst row
    const int dy = by * 32;   // d dimension
    #pragma unroll
    for (int i = 0; i < 2; i++) {
        int q   = tid + i * 256;      // 0..511
        int row = q >> 4;             // d-local 0..31
        int c4  = (q & 15) * 4;       // p-local (float4 aligned)
        int p   = px + c4;
        float4 v;
        if (p < ncols)   // ncols % 4 == 0 -> whole float4 in bounds
            v = *reinterpret_cast<const float4*>(&s[(size_t)(dy + row) * ncols + p]);
        else
            v = make_float4(0.f, 0.f, 0.f, 0.f);
        tile[row][c4]     = v.x * scale;
        tile[row][c4 + 1] = v.y * scale;
        tile[row][c4 + 2] = v.z * scale;
        tile[row][c4 + 3] = v.w * scale;
    }
    __syncthreads();
    #pragma unroll
    for (int i = 0; i < 4; i++) {
        int q    = tid + i * 256;     // 0..1023
        int prow = q >> 4;            // p-local 0..63
        int pr   = q & 15;            // d-pair 0..15
        int p = px + prow;
        if (p < nrows_pad) {
            __half2 h = __floats2half2_rn(tile[pr * 2][prow], tile[pr * 2 + 1][prow]);
            *reinterpret_cast<__half2*>(d + (size_t)p * DIMD + dy + pr * 2) = h;
        }
    }
}

__global__ __launch_bounds__(256)
void prep_all_kernel(const float* __restrict__ feats_view1,
                     const float* __restrict__ pos_feats1,
                     const float* __restrict__ pos_feats2,
                     const float* __restrict__ pl1,
                     const float* __restrict__ pl2,
                     const float* __restrict__ npl,
                     __half* __restrict__ pA,
                     __half* __restrict__ pB) {
    __shared__ float tile[32][65];
    const int bid = blockIdx.x;
    const int tid = threadIdx.x;

    if (bid < NB_CONVB) {
        int bz  = bid / (NB_CONVB / BATCH);
        int rem = bid % (NB_CONVB / BATCH);
        int by  = rem / (NN / 64);
        int bx  = rem % (NN / 64);
        conv_section64(feats_view1 + (size_t)bz * DIMD * NN,
                       pB + (size_t)bz * NN * DIMD,
                       NN, NN, 1.0f, bx, by, tid, tile);
    } else if (bid < NB_CONVB + NB_CONVA) {
        int b2  = bid - NB_CONVB;
        int bz  = b2 / (NB_CONVA / BATCH);
        int rem = b2 % (NB_CONVA / BATCH);
        int by  = rem / (NP_PAD / 64);
        int bx  = rem % (NP_PAD / 64);
        conv_section64(pos_feats1 + (size_t)bz * DIMD * NP,
                       pA + (size_t)bz * NP_PAD * DIMD,
                       NP, NP_PAD, A_SCALE, bx, by, tid, tile);
    } else if (bid < NB_CONVB + NB_CONVA + NB_NEG) {
        int b3 = bid - NB_CONVB - NB_CONVA;
        int b  = b3 / (NB_NEG / BATCH);
        int n  = (b3 % (NB_NEG / BATCH)) * 256 + tid;
        const float* nplb = npl + (size_t)b * NCLS * NN;
        float best = -1e30f; int bi = 0;
        #pragma unroll
        for (int c = 0; c < NCLS; c++) {
            float v = nplb[c * NN + n];
            if (v > best) { best = v; bi = c; }
        }
        g_neg_labels[b][n] = bi;
    } else {
        int b4 = bid - NB_CONVB - NB_CONVA - NB_NEG;
        int b  = b4 / (NB_ANCH / BATCH);
        int p  = (b4 % (NB_ANCH / BATCH)) * 256 + tid;
        if (p >= NP) return;

        const float* pl1b = pl1 + (size_t)b * NCLS * NP;
        const float* pl2b = pl2 + (size_t)b * NCLS * NP;

        float best = -1e30f; int bi = 0;
        #pragma unroll
        for (int c = 0; c < NCLS; c++) {
            float v = pl1b[c * NP + p];
            if (v > best) { best = v; bi = c; }
        }
        g_labels1[b][p] = bi;

        int mi = -1;
        #pragma unroll
        for (int c = 0; c < NCLS; c++) {
            float a = pl1b[c * NP + p];
            float q = pl2b[c * NP + p];
            if (mi < 0 && (a < q) && (q > GAMMA)) mi = c;
        }
        g_mask1[b][p] = (mi < 0) ? 0.0f : (float)mi;

        const float* f1b = pos_feats1 + (size_t)b * DIMD * NP;
        const float* f2b = pos_feats2 + (size_t)b * DIMD * NP;
        float acc = 0.0f;
        #pragma unroll 8
        for (int d = 0; d < DIMD; d++)
            acc += f1b[d * NP + p] * f2b[d * NP + p];
        g_pos1[b][p] = acc * INV_TEMP;

        g_neg_logits[b][p] = 0.0f;
    }
}

// ---------------------------------------------------------------------------
// SMEM layout (bytes, from 1024-aligned base) -- tcgen05 path
// ---------------------------------------------------------------------------
#define OFF_A     0u
#define OFF_B     32768u
#define OFF_NLAB  98304u      // NTPC * 128 ints
#define OFF_TPTR  107520u
#define OFF_MBAR  107528u
#define SMEM_REQ  (107544 + 1024)

#if HAVE_TC5
// ---------------------------------------------------------------------------
// tcgen05 helpers (sm_103a-only pass)
// ---------------------------------------------------------------------------
static constexpr uint64_t SMEM_DESC_BASE_SW128 =
    (uint64_t(2)  << 61) | (uint64_t(1) << 46) | (uint64_t(64) << 32) | (uint64_t(1) << 16);

__device__ __forceinline__ uint64_t make_desc(uint32_t saddr) {
    return SMEM_DESC_BASE_SW128 | ((uint64_t)(saddr >> 4) & 0x3FFF);
}

__device__ __forceinline__ bool elect1() {
    uint32_t p;
    asm volatile("{\n\t.reg .pred p;\n\telect.sync _|p, 0xFFFFFFFF;\n\tselp.b32 %0, 1, 0, p;\n\t}"
                 : "=r"(p));
    return p != 0;
}

__device__ __forceinline__ void mma_f16_ss(uint32_t d, uint64_t a, uint64_t b,
                                           uint32_t en) {
    asm volatile(
        "{\n\t.reg .pred p;\n\tsetp.ne.u32 p, %4, 0;\n\t"
        "tcgen05.mma.cta_group::1.kind::f16 [%0], %1, %2, %3, {%5,%5,%5,%5}, p;\n\t}"
        :: "r"(d), "l"(a), "l"(b), "r"(MMA_IDESC), "r"(en), "r"(0u)
        : "memory");
}

__device__ __forceinline__ void mbar_init(uint32_t a, uint32_t cnt) {
    asm volatile("mbarrier.init.shared.b64 [%0], %1;" :: "r"(a), "r"(cnt) : "memory");
}
__device__ __forceinline__ void mbar_wait(uint32_t a, uint32_t ph) {
    asm volatile(
        "{\n\t.reg .pred P1;\n\t"
        "W0_%=:\n\t"
        "mbarrier.try_wait.parity.acquire.cta.shared::cta.b64 P1, [%0], %1, 0x989680;\n\t"
        "@P1 bra W1_%=;\n\t"
        "bra W0_%=;\n\t"
        "W1_%=:\n\t}"
        :: "r"(a), "r"(ph) : "memory");
}

#define TC_ALLOC(sa, n)  asm volatile("tcgen05.alloc.cta_group::1.sync.aligned.shared::cta.b32 [%0], %1;" :: "r"(sa), "r"(n) : "memory")
#define TC_RELINQ()      asm volatile("tcgen05.relinquish_alloc_permit.cta_group::1.sync.aligned;")
#define TC_DEALLOC(t, n) asm volatile("tcgen05.dealloc.cta_group::1.sync.aligned.b32 %0, %1;" :: "r"(t), "r"(n))
#define TC_COMMIT(mb)    asm volatile("tcgen05.commit.cta_group::1.mbarrier::arrive::one.shared::cluster.b64 [%0];" :: "r"(mb) : "memory")
#define TC_WAIT_LD()     asm volatile("tcgen05.wait::ld.sync.aligned;" ::: "memory")
#define TC_FENCE_AFTER() asm volatile("tcgen05.fence::after_thread_sync;" ::: "memory")
#define TC_FENCE_BEFORE() asm volatile("tcgen05.fence::before_thread_sync;" ::: "memory")
#define PROXY_FENCE()    asm volatile("fence.proxy.async.shared::cta;" ::: "memory")
#define CP_COMMIT()      asm volatile("cp.async.commit_group;" ::: "memory")
#define CP_WAIT0()       asm volatile("cp.async.wait_group 0;" ::: "memory")
#define CP_WAIT1()       asm volatile("cp.async.wait_group 1;" ::: "memory")

#define LDTM_X32(r, a) \
    asm volatile("tcgen05.ld.sync.aligned.32x32b.x32.b32 " \
        "{%0, %1, %2, %3, %4, %5, %6, %7, " \
        " %8, %9, %10, %11, %12, %13, %14, %15, " \
        " %16, %17, %18, %19, %20, %21, %22, %23, " \
        " %24, %25, %26, %27, %28, %29, %30, %31}, [%32];" \
        : "=r"((r)[0]),  "=r"((r)[1]),  "=r"((r)[2]),  "=r"((r)[3]), \
          "=r"((r)[4]),  "=r"((r)[5]),  "=r"((r)[6]),  "=r"((r)[7]), \
          "=r"((r)[8]),  "=r"((r)[9]),  "=r"((r)[10]), "=r"((r)[11]), \
          "=r"((r)[12]), "=r"((r)[13]), "=r"((r)[14]), "=r"((r)[15]), \
          "=r"((r)[16]), "=r"((r)[17]), "=r"((r)[18]), "=r"((r)[19]), \
          "=r"((r)[20]), "=r"((r)[21]), "=r"((r)[22]), "=r"((r)[23]), \
          "=r"((r)[24]), "=r"((r)[25]), "=r"((r)[26]), "=r"((r)[27]), \
          "=r"((r)[28]), "=r"((r)[29]), "=r"((r)[30]), "=r"((r)[31]) \
        : "r"(a))

// cp.async a [128 rows x 128 f16] row-major global tile into K-blocked
// SW128 SMEM: two blocks of [128 rows x 64 f16] (128B rows, XOR swizzle).
__device__ __forceinline__ void cp_tile128(const __half* __restrict__ g,
                                           uint32_t s_base, int tid) {
    #pragma unroll
    for (int i = 0; i < 8; i++) {
        int q = tid + i * 256;         // 16B-chunk index, 2048 total
        int r = q >> 4;                // row 0..127
        int c = q & 15;                // chunk 0..15
        int blk = c >> 3;
        int cc  = (c & 7) ^ (r & 7);
        uint32_t sa = s_base + blk * 16384u + (uint32_t)r * 128u + (uint32_t)cc * 16u;
        const void* ga = (const void*)(g + (size_t)r * 128 + c * 8);
        asm volatile("cp.async.cg.shared.global [%0], [%1], 16;"
                     :: "r"(sa), "l"(ga) : "memory");
    }
}

// exp2 of two fp32 values via one MUFU op (f16x2): inputs are log2-domain
// scores (|x| small); independent per-element rounding -> error ~1e-5 on sums.
__device__ __forceinline__ float2 ex2_pair(float lo, float hi) {
    uint32_t h;
    asm("cvt.rn.f16x2.f32 %0, %1, %2;" : "=r"(h) : "f"(hi), "f"(lo));
    asm("ex2.approx.f16x2 %0, %0;" : "+r"(h));
    return __half22float2(*reinterpret_cast<__half2*>(&h));
}
#endif  // HAVE_TC5

#if !HAVE_TC5
// ---------------------------------------------------------------------------
// Fallback helpers: mma.sync m16n8k16 f16 (compiles on any >= sm_80 target)
// ---------------------------------------------------------------------------
__device__ __forceinline__ void ldmx4(uint32_t* r, uint32_t saddr) {
    asm volatile("ldmatrix.sync.aligned.m8n8.x4.shared.b16 {%0,%1,%2,%3}, [%4];"
                 : "=r"(r[0]), "=r"(r[1]), "=r"(r[2]), "=r"(r[3]) : "r"(saddr));
}
__device__ __forceinline__ void mma16816(float* c, const uint32_t* a, const uint32_t* b) {
    asm volatile("mma.sync.aligned.m16n8k16.row.col.f32.f16.f16.f32 "
                 "{%0,%1,%2,%3}, {%4,%5,%6,%7}, {%8,%9}, {%0,%1,%2,%3};"
                 : "+f"(c[0]), "+f"(c[1]), "+f"(c[2]), "+f"(c[3])
                 : "r"(a[0]), "r"(a[1]), "r"(a[2]), "r"(a[3]), "r"(b[0]), "r"(b[1]));
}
// swizzled element offset in a flat [r][128] f16 tile (16B-chunk XOR swizzle)
__device__ __forceinline__ int swz(int r, int k) {
    return r * 128 + ((((k) >> 3) ^ (r & 7)) << 3) + (k & 7);
}
#endif  // !HAVE_TC5

// ---------------------------------------------------------------------------
// GEMM + fused masked-exp row-sum epilogue. One kernel name, two bodies:
// tcgen05 (sm_103a cubin) or mma.sync (virtual-arch / JIT fallback).
// Grid: (GROUPS_N, NP_PAD/128, BATCH), 256 threads, SMEM_REQ dynamic smem.
// ---------------------------------------------------------------------------
__global__ __launch_bounds__(256, 2)
void neg_gemm_kernel() {
    extern __shared__ __align__(16) uint8_t dynsmem[];
    uint8_t* smem = (uint8_t*)(((uintptr_t)dynsmem + 1023) & ~(uintptr_t)1023);

    const int b      = blockIdx.z;
    const int p0     = blockIdx.y * 128;
    const int n_base = blockIdx.x * (NTPC * 128);
    const int tid    = threadIdx.x;
    const int wid    = tid >> 5;
    const int lane   = tid & 31;

#if HAVE_TC5
    // ======================= tcgen05 pipelined path =======================
    const uint32_t sb    = (uint32_t)__cvta_generic_to_shared(smem);
    const uint32_t mbar0 = sb + OFF_MBAR;
    const uint32_t mbar1 = sb + OFF_MBAR + 8;
    int* nlabAll = (int*)(smem + OFF_NLAB);

    if (wid == 0) {
        TC_ALLOC(sb + OFF_TPTR, 256u);
        TC_RELINQ();
    }
    if (tid == 0) { mbar_init(mbar0, 1); mbar_init(mbar1, 1); }

    // prologue: async-load A + B0 (group 0), B1 (group 1); labels for all tiles
    cp_tile128(&g_Ah[b][p0][0], sb + OFF_A, tid);
    cp_tile128(&g_Bh[b][n_base][0], sb + OFF_B, tid);
    CP_COMMIT();
    cp_tile128(&g_Bh[b][n_base + 128][0], sb + OFF_B + 32768u, tid);
    CP_COMMIT();
    #pragma unroll
    for (int i = 0; i < NTPC * 128 / 256; i++)
        nlabAll[tid + i * 256] = g_neg_labels[b][n_base + tid + i * 256];

    CP_WAIT1();        // A + B0 resident
    PROXY_FENCE();
    __syncthreads();

    const uint32_t tmem_base = *reinterpret_cast<uint32_t*>(smem + OFF_TPTR);
    const uint64_t adesc = make_desc(sb + OFF_A);

    // issue MMA for tile 0
    if (wid == 0) {
        TC_FENCE_AFTER();
        if (elect1()) {
            uint64_t bdesc = make_desc(sb + OFF_B);
            #pragma unroll
            for (int kk = 0; kk < 8; kk++) {
                uint64_t koff = (uint64_t)((kk >> 2) * 1024 + (kk & 3) * 2);
                mma_f16_ss(tmem_base, adesc + koff, bdesc + koff, kk > 0);
            }
            TC_COMMIT(mbar0);
        }
    }

    const int myrow = (wid & 3) * 32 + lane;
    const int myp   = p0 + myrow;
    const int lp    = (myp < NP) ? g_labels1[b][myp] : -1;
    float rs0 = 0.0f, rs1 = 0.0f;
    const int cbase = (wid >> 2) * 64;  // warpgroup n-column split

    for (int nt = 1; nt <= NTPC; nt++) {
        const int prev = nt - 1;
        const uint32_t dtm_prev = tmem_base + (prev & 1) * 128;

        // MMA prev done (issued one epilogue ago -> fast-path wait)
        mbar_wait((prev & 1) ? mbar1 : mbar0, (prev >> 1) & 1);
        TC_FENCE_AFTER();

        // Early-issue first LDTM chunk: its ~228-cyc latency hides under the
        // prefetch + sync + MMA-issue work below. Only r0 (32 regs) spans the
        // sync -- same peak register pressure as the R13 schedule.
        uint32_t r0[32];
        LDTM_X32(r0, dtm_prev + cbase);

        if (nt < NTPC) {
            // prefetch B[nt+1] into the buffer MMA prev just released
            if (nt + 1 < NTPC) {
                cp_tile128(&g_Bh[b][n_base + (nt + 1) * 128][0],
                           sb + OFF_B + (uint32_t)((nt + 1) & 1) * 32768u, tid);
                CP_COMMIT();
                CP_WAIT1();      // B[nt] resident
            } else {
                CP_WAIT0();      // B[nt] resident, no more prefetch
            }
            PROXY_FENCE();
        }
        __syncthreads();

        if (nt < NTPC && wid == 0) {
            TC_FENCE_AFTER();
            if (elect1()) {
                uint64_t bdesc = make_desc(sb + OFF_B + (uint32_t)(nt & 1) * 32768u);
                uint32_t dtm = tmem_base + (nt & 1) * 128;
                #pragma unroll
                for (int kk = 0; kk < 8; kk++) {
                    uint64_t koff = (uint64_t)((kk >> 2) * 1024 + (kk & 3) * 2);
                    mma_f16_ss(dtm, adesc + koff, bdesc + koff, kk > 0);
                }
                TC_COMMIT((nt & 1) ? mbar1 : mbar0);
            }
        }

        // ---- epilogue tile prev (overlaps MMA nt + prefetch B nt+1) ----
        const int* nl = nlabAll + prev * 128;
        TC_WAIT_LD();                      // r0 ready (latency already hidden)
        uint32_t r1[32];
        LDTM_X32(r1, dtm_prev + cbase + 32);   // r1 latency hides under r0 math
        #pragma unroll
        for (int j = 0; j < 32; j += 2) {
            float2 e = ex2_pair(__uint_as_float(r0[j]), __uint_as_float(r0[j + 1]));
            rs0 += (lp != nl[cbase + j])     ? e.x : 0.0f;
            rs1 += (lp != nl[cbase + j + 1]) ? e.y : 0.0f;
        }
        TC_WAIT_LD();
        #pragma unroll
        for (int j = 0; j < 32; j += 2) {
            float2 e = ex2_pair(__uint_as_float(r1[j]), __uint_as_float(r1[j + 1]));
            rs0 += (lp != nl[cbase + 32 + j])     ? e.x : 0.0f;
            rs1 += (lp != nl[cbase + 32 + j + 1]) ? e.y : 0.0f;
        }
        TC_FENCE_BEFORE();
    }

    if (myp < NP)
        atomicAdd(&g_neg_logits[b][myp], rs0 + rs1);

    __syncthreads();
    if (wid == 0) TC_DEALLOC(tmem_base, 256u);

#else
    // ======================= mma.sync fallback path =======================
    __half* Asm = (__half*)smem;             // 32KB (flat [128][128] swz)
    __half* Bsm = (__half*)(smem + 32768u);  // 32KB
    int* nlab = (int*)(smem + 65536u);       // 128 ints

    const int wm = wid & 3;    // m sub-block (32 rows)
    const int wn = wid >> 2;   // n sub-block (64 cols)

    const __half* Ag = &g_Ah[b][p0][0];
    #pragma unroll
    for (int i = 0; i < 8; i++) {
        int q = tid + i * 256;
        int r = q >> 4;
        int c = q & 15;
        uint4 v = *reinterpret_cast<const uint4*>(Ag + (size_t)r * 128 + c * 8);
        int sc = c ^ (r & 7);
        *reinterpret_cast<uint4*>(Asm + r * 128 + sc * 8) = v;
    }

    int lp2[2][2];
    #pragma unroll
    for (int mi = 0; mi < 2; mi++) {
        int base = p0 + wm * 32 + mi * 16 + (lane >> 2);
        lp2[mi][0] = (base     < NP) ? g_labels1[b][base]     : -1;
        lp2[mi][1] = (base + 8 < NP) ? g_labels1[b][base + 8] : -1;
    }
    float rs[2][2] = {{0.f, 0.f}, {0.f, 0.f}};

    const uint32_t asmb = (uint32_t)__cvta_generic_to_shared(Asm);
    const uint32_t bsmb = (uint32_t)__cvta_generic_to_shared(Bsm);

    for (int nt = 0; nt < NTPC; nt++) {
        const int n0 = n_base + nt * 128;
        __syncthreads();
        const __half* Bg = &g_Bh[b][n0][0];
        #pragma unroll
        for (int i = 0; i < 8; i++) {
            int q = tid + i * 256;
            int r = q >> 4;
            int c = q & 15;
            uint4 v = *reinterpret_cast<const uint4*>(Bg + (size_t)r * 128 + c * 8);
            int sc = c ^ (r & 7);
            *reinterpret_cast<uint4*>(Bsm + r * 128 + sc * 8) = v;
        }
        if (tid < 128) nlab[tid] = g_neg_labels[b][n0 + tid];
        __syncthreads();

        float acc[2][8][4];
        #pragma unroll
        for (int mi = 0; mi < 2; mi++)
            #pragma unroll
            for (int ni = 0; ni < 8; ni++)
                #pragma unroll
                for (int x = 0; x < 4; x++) acc[mi][ni][x] = 0.0f;

        #pragma unroll
        for (int kk = 0; kk < 8; kk++) {
            const int k0 = kk * 16;
            uint32_t afr[2][4];
            #pragma unroll
            for (int mi = 0; mi < 2; mi++) {
                int row = wm * 32 + mi * 16 + (lane & 7) + 8 * ((lane >> 3) & 1);
                int k8  = k0 + 8 * (lane >> 4);
                ldmx4(afr[mi], asmb + 2 * swz(row, k8));
            }
            uint32_t bfr[8][2];
            #pragma unroll
            for (int nj = 0; nj < 4; nj++) {
                int nrow = wn * 64 + nj * 16 + (lane & 7) + 8 * (lane >> 4);
                int k8   = k0 + 8 * ((lane >> 3) & 1);
                uint32_t r4[4];
                ldmx4(r4, bsmb + 2 * swz(nrow, k8));
                bfr[nj * 2][0]     = r4[0]; bfr[nj * 2][1]     = r4[1];
                bfr[nj * 2 + 1][0] = r4[2]; bfr[nj * 2 + 1][1] = r4[3];
            }
            #pragma unroll
            for (int mi = 0; mi < 2; mi++)
                #pragma unroll
                for (int ni = 0; ni < 8; ni++)
                    mma16816(acc[mi][ni], afr[mi], bfr[ni]);
        }

        #pragma unroll
        for (int ni = 0; ni < 8; ni++) {
            int c0  = wn * 64 + ni * 8 + 2 * (lane & 3);
            int ln0 = nlab[c0];
            int ln1 = nlab[c0 + 1];
            #pragma unroll
            for (int mi = 0; mi < 2; mi++) {
                float e0 = ex2f(acc[mi][ni][0]);
                float e1 = ex2f(acc[mi][ni][1]);
                float e2 = ex2f(acc[mi][ni][2]);
                float e3 = ex2f(acc[mi][ni][3]);
                rs[mi][0] += (lp2[mi][0] != ln0 ? e0 : 0.f) + (lp2[mi][0] != ln1 ? e1 : 0.f);
                rs[mi][1] += (lp2[mi][1] != ln0 ? e2 : 0.f) + (lp2[mi][1] != ln1 ? e3 : 0.f);
            }
        }
    }

    #pragma unroll
    for (int mi = 0; mi < 2; mi++)
        #pragma unroll
        for (int h = 0; h < 2; h++) {
            float s = rs[mi][h];
            s += __shfl_xor_sync(0xffffffffu, s, 1);
            s += __shfl_xor_sync(0xffffffffu, s, 2);
            int p = p0 + wm * 32 + mi * 16 + (lane >> 2) + h * 8;
            if ((lane & 3) == 0 && p < NP)
                atomicAdd(&g_neg_logits[b][p], s);
        }
#endif
}

// ---------------------------------------------------------------------------
// Finalize (fast intrinsics; tiny kernel)
// ---------------------------------------------------------------------------
__global__ void finalize_kernel(float* __restrict__ out) {
    __shared__ float s_num[1024];
    __shared__ float s_den[1024];
    const int tid = threadIdx.x;
    float total = 0.0f;

    for (int b = 0; b < BATCH; b++) {
        float num = 0.0f, den = 0.0f;
        for (int p = tid; p < NP; p += 1024) {
            float pe  = __expf(g_pos1[b][p]);
            float neg = g_neg_logits[b][p];
            float lossn = -__logf(pe / (pe + neg + EPS) + EPS);
            float m = g_mask1[b][p];
            num += m * lossn;
            den += m;
        }
        s_num[tid] = num; s_den[tid] = den;
        __syncthreads();
        for (int s = 512; s > 0; s >>= 1) {
            if (tid < s) { s_num[tid] += s_num[tid + s]; s_den[tid] += s_den[tid + s]; }
            __syncthreads();
        }
        if (tid == 0) total += s_num[0] / (s_den[0] + EPS);
        __syncthreads();
    }
    if (tid == 0) out[0] = 0.1f * total;
}

// ---------------------------------------------------------------------------
extern "C" void kernel_launch(void* const* d_in, const int* in_sizes, int n_in,
                              void* d_out, int out_size) {
    const float* feats_view1 = (const float*)d_in[0];  // [2,128,240,240]
    const float* pos_feats1  = (const float*)d_in[1];  // [2,128,60,60]
    const float* pos_feats2  = (const float*)d_in[2];  // [2,128,60,60]
    const float* plog1       = (const float*)d_in[3];  // [2,19,60,60]
    const float* plog2       = (const float*)d_in[4];  // [2,19,60,60]
    const float* neg_plog    = (const float*)d_in[5];  // [2,19,240,240]
    float* out = (float*)d_out;

    static __half* pA = nullptr;
    static __half* pB = nullptr;
    if (!pA) { cudaGetSymbolAddress((void**)&pA, g_Ah); }
    if (!pB) { cudaGetSymbolAddress((void**)&pB, g_Bh); }

    static bool attr_set = false;
    if (!attr_set) {
        cudaFuncSetAttribute(neg_gemm_kernel,
                             cudaFuncAttributeMaxDynamicSharedMemorySize, SMEM_REQ);
        attr_set = true;
    }

    prep_all_kernel<<<NB_TOTAL, 256>>>(feats_view1, pos_feats1, pos_feats2,
                                       plog1, plog2, neg_plog, pA, pB);
    {
        dim3 grid(GROUPS_N, NP_PAD / 128, BATCH);   // (25, 29, 2)
        neg_gemm_kernel<<<grid, 256, SMEM_REQ>>>();
    }
    finalize_kernel<<<1, 1024>>>(out);
}